// round 4
// baseline (speedup 1.0000x reference)
#include <cuda_runtime.h>
#include <cuda_bf16.h>
#include <cstdint>

// Problem constants (fixed by the reference)
#define NB 32      // batch
#define NZ 4000    // nodes
#define NIN 32     // in features
#define NH 64      // hidden
#define NE 64000   // edges

#define NBLK 148   // one block per SM -> co-residency guaranteed
#define NTHR 256
#define GT (NBLK * NTHR)        // 37888 grid threads
#define NY (NB * NZ * NIN / 4)  // 1,024,000 float4 loads of x

// Scratch (device globals; no allocations allowed)
__device__ float  g_y[NZ * NB];      // y[z*NB + b] = x[b,z,:] . v
__device__ int    g_deg[NZ];         // in-degree (EXCLUDING self-loop)
__device__ int    g_rank[NE];        // rank of edge within its dst bucket
__device__ int    g_rowptr[NZ + 1];  // CSR row offsets (by dst)
__device__ float  g_dinv[NZ];        // rsqrt(deg+1)
__device__ float2 g_csr[NE];         // per edge: (.x = src as int bits, .y = dinv[src])
__device__ __align__(16) float g_v[NIN];  // W @ fc_W
__device__ float  g_const;           // b . fc_W + fc_b

// Monotonic grid barrier state (never reset; zero-initialized at module load)
__device__ unsigned g_bar_count;
__device__ unsigned g_bar_gen;

// Sense-free monotonic grid barrier. Thread 0 of each block arrives; the
// 148th arrival bumps the generation; others spin on it (L2 atomic reads,
// no L1 staleness). __threadfence (gpu scope) on both sides orders all
// phase writes/reads and invalidates L1D (CCTL.IVALL on sm_103a).
__device__ __forceinline__ void grid_barrier(unsigned target) {
    __syncthreads();
    if (threadIdx.x == 0) {
        __threadfence();
        unsigned prev = atomicAdd(&g_bar_count, 1u);
        if ((prev + 1u) % NBLK == 0u) {
            atomicAdd(&g_bar_gen, 1u);     // release
        } else {
            unsigned g;
            do { g = atomicAdd(&g_bar_gen, 0u); } while ((int)(g - target) < 0);
        }
        __threadfence();
    }
    __syncthreads();
}

__global__ __launch_bounds__(NTHR, 1)
void k_fused(const float* __restrict__ x,
             const int* __restrict__ src,
             const int* __restrict__ dst,
             const float* __restrict__ W,
             const float* __restrict__ bias,
             const float* __restrict__ fcW,
             const float* __restrict__ fcb,
             float* __restrict__ out) {
    const int gtid = blockIdx.x * NTHR + threadIdx.x;

    // Barrier generation base for this launch. Read by thread 0 of every
    // block BEFORE any block can release barrier 1 (each block reads before
    // arriving), so the value is stable.
    unsigned base = 0;
    if (threadIdx.x == 0) base = atomicAdd(&g_bar_gen, 0u);

    // ---------------- Phase A: zero deg; block 0 computes v and const -----
    for (int z = gtid; z < NZ; z += GT) g_deg[z] = 0;
    if (blockIdx.x == 0) {
        if (threadIdx.x < NIN) {
            float s = 0.f;
            #pragma unroll
            for (int h = 0; h < NH; ++h) s += W[threadIdx.x * NH + h] * fcW[h];
            g_v[threadIdx.x] = s;
        } else if (threadIdx.x == NIN) {
            float s = fcb[0];
            #pragma unroll
            for (int h = 0; h < NH; ++h) s += bias[h] * fcW[h];
            g_const = s;
        }
    }
    grid_barrier(base + 1u);

    // ---------------- Phase B: histogram (+rank capture) and ydot ---------
    for (int e = gtid; e < NE; e += GT) {
        int d = dst[e];
        g_rank[e] = atomicAdd(&g_deg[d], 1);   // rank within dst bucket, free
    }
    {
        const float4 vv = reinterpret_cast<const float4*>(g_v)[gtid & 7];
        const bool leader = (gtid & 7) == 0;
        const float4* xv = reinterpret_cast<const float4*>(x);
        for (int i = gtid; i < NY; i += GT) {   // GT % 8 == 0 -> (i&7) invariant
            float4 a = xv[i];
            float p = a.x * vv.x + a.y * vv.y + a.z * vv.z + a.w * vv.w;
            p += __shfl_xor_sync(0xFFFFFFFFu, p, 1);
            p += __shfl_xor_sync(0xFFFFFFFFu, p, 2);
            p += __shfl_xor_sync(0xFFFFFFFFu, p, 4);
            if (leader) {
                int f = i >> 3;              // row index = b*NZ + z
                int b = f / NZ;
                int z = f - b * NZ;
                g_y[z * NB + b] = p;
            }
        }
    }
    grid_barrier(base + 2u);

    // ---------------- Phase C: dinv + exclusive scan (block 0) ------------
    for (int z = gtid; z < NZ; z += GT)
        g_dinv[z] = rsqrtf((float)(__ldcg(&g_deg[z]) + 1));
    if (blockIdx.x == 0) {
        __shared__ int warp_sums[8];
        const int CH = 16;                    // 256*16 = 4096 >= NZ
        int t    = threadIdx.x;
        int lane = t & 31;
        int wid  = t >> 5;
        int bse  = t * CH;

        int local[CH];
        int s = 0;
        #pragma unroll
        for (int j = 0; j < CH; ++j) {
            int z = bse + j;
            int d = (z < NZ) ? __ldcg(&g_deg[z]) : 0;
            local[j] = s;
            s += d;
        }
        int v = s;
        #pragma unroll
        for (int o = 1; o < 32; o <<= 1) {
            int n = __shfl_up_sync(0xFFFFFFFFu, v, o);
            if (lane >= o) v += n;
        }
        if (lane == 31) warp_sums[wid] = v;
        __syncthreads();
        if (wid == 0) {
            int wv = (lane < 8) ? warp_sums[lane] : 0;
            #pragma unroll
            for (int o = 1; o < 8; o <<= 1) {
                int n = __shfl_up_sync(0xFFFFFFFFu, wv, o);
                if (lane >= o) wv += n;
            }
            if (lane < 8) warp_sums[lane] = wv;
        }
        __syncthreads();
        int thread_excl = (v - s) + (wid > 0 ? warp_sums[wid - 1] : 0);
        #pragma unroll
        for (int j = 0; j < CH; ++j) {
            int z = bse + j;
            if (z < NZ) g_rowptr[z] = thread_excl + local[j];
        }
        if (t == 0) g_rowptr[NZ] = NE;
    }
    grid_barrier(base + 3u);

    // ---------------- Phase D: CSR fill (no atomics) -----------------------
    for (int e = gtid; e < NE; e += GT) {
        int s = src[e];
        int d = dst[e];
        int slot = g_rowptr[d] + g_rank[e];
        g_csr[slot] = make_float2(__int_as_float(s), g_dinv[s]);
    }
    grid_barrier(base + 4u);

    // ---------------- Phase E: gather + self-loop + transposed store ------
    {
        int warp = gtid >> 5;
        int lane = gtid & 31;                 // batch index
        const int NW = GT / 32;               // 1184 warps
        float c = g_const;
        for (int z = warp; z < NZ; z += NW) {
            int beg = g_rowptr[z];
            int end = g_rowptr[z + 1];
            float val = 0.f;
            int i = beg;
            for (; i + 4 <= end; i += 4) {
                float2 e0 = g_csr[i + 0];
                float2 e1 = g_csr[i + 1];
                float2 e2 = g_csr[i + 2];
                float2 e3 = g_csr[i + 3];
                float y0 = g_y[__float_as_int(e0.x) * NB + lane];
                float y1 = g_y[__float_as_int(e1.x) * NB + lane];
                float y2 = g_y[__float_as_int(e2.x) * NB + lane];
                float y3 = g_y[__float_as_int(e3.x) * NB + lane];
                val += e0.y * y0 + e1.y * y1 + e2.y * y2 + e3.y * y3;
            }
            for (; i < end; ++i) {
                float2 e = g_csr[i];
                val += e.y * g_y[__float_as_int(e.x) * NB + lane];
            }
            float dz = g_dinv[z];
            val = dz * (val + dz * g_y[z * NB + lane]);   // + self-loop
            out[(size_t)lane * NZ + z] = val + c;
        }
    }
}

// ---------------------------------------------------------------------------
extern "C" void kernel_launch(void* const* d_in, const int* in_sizes, int n_in,
                              void* d_out, int out_size) {
    const float* x    = (const float*)d_in[0];   // [32,4000,32]
    const int*   ei   = (const int*)  d_in[1];   // [2,64000]
    const float* W    = (const float*)d_in[2];   // [32,64]
    const float* bias = (const float*)d_in[3];   // [64]
    const float* fcW  = (const float*)d_in[4];   // [64]
    const float* fcb  = (const float*)d_in[5];   // [1]
    float* out = (float*)d_out;                  // [32,4000]

    k_fused<<<NBLK, NTHR>>>(x, ei, ei + NE, W, bias, fcW, fcb, out);
}

// round 5
// speedup vs baseline: 1.3148x; 1.3148x over previous
#include <cuda_runtime.h>
#include <cuda_bf16.h>
#include <cstdint>

// Problem constants (fixed by the reference)
#define NB 32      // batch
#define NZ 4000    // nodes
#define NIN 32     // in features
#define NH 64      // hidden
#define NE 64000   // edges

#define NBLK 148   // one block per SM -> co-residency guaranteed
#define NTHR 1024  // 32 warps/SM
#define GT (NBLK * NTHR)        // 151,552 grid threads
#define NY (NB * NZ * NIN / 4)  // 1,024,000 float4 loads of x
#define NFULL 6                 // full grid strides in ydot: 6*GT = 909,312
#define NYTAIL (NY - NFULL * GT)  // 114,688 (divisible by 8)

// Scratch (device globals; no allocations allowed)
__device__ float  g_y[NZ * NB];      // y[z*NB + b] = x[b,z,:] . v
__device__ int    g_deg[NZ];         // in-degree (EXCLUDING self-loop)
__device__ int    g_rank[NE];        // rank of edge within its dst bucket
__device__ int    g_rowptr[NZ + 1];  // CSR row offsets (by dst)
__device__ float  g_dinv[NZ];        // rsqrt(deg+1)
__device__ float2 g_csr[NE];         // per edge: (.x = src as int bits, .y = dinv[src])
__device__ __align__(16) float g_v[NIN];  // W @ fc_W
__device__ float  g_const;           // b . fc_W + fc_b

// Monotonic grid barrier state (never reset; zero-initialized at module load)
__device__ unsigned g_bar_count;
__device__ unsigned g_bar_gen;

// Sense-free monotonic grid barrier (1 block per SM, always co-resident).
__device__ __forceinline__ void grid_barrier(unsigned target) {
    __syncthreads();
    if (threadIdx.x == 0) {
        __threadfence();
        unsigned prev = atomicAdd(&g_bar_count, 1u);
        if ((prev + 1u) % NBLK == 0u) {
            atomicAdd(&g_bar_gen, 1u);     // release
        } else {
            unsigned g;
            do { g = atomicAdd(&g_bar_gen, 0u); } while ((int)(g - target) < 0);
        }
        __threadfence();
    }
    __syncthreads();
}

__device__ __forceinline__ float dot8(float4 a, float4 v) {
    float p = a.x * v.x + a.y * v.y + a.z * v.z + a.w * v.w;
    p += __shfl_xor_sync(0xFFFFFFFFu, p, 1);
    p += __shfl_xor_sync(0xFFFFFFFFu, p, 2);
    p += __shfl_xor_sync(0xFFFFFFFFu, p, 4);
    return p;
}

__device__ __forceinline__ void emit_y(int i, float p) {
    int f = i >> 3;              // row index = b*NZ + z
    int b = f / NZ;
    int z = f - b * NZ;
    g_y[z * NB + b] = p;
}

__global__ __launch_bounds__(NTHR, 1)
void k_fused(const float* __restrict__ x,
             const int* __restrict__ src,
             const int* __restrict__ dst,
             const float* __restrict__ W,
             const float* __restrict__ bias,
             const float* __restrict__ fcW,
             const float* __restrict__ fcb,
             float* __restrict__ out) {
    const int gtid = blockIdx.x * NTHR + threadIdx.x;

    // Barrier generation base for this launch (stable: every block reads it
    // before arriving at barrier 1, so before any block can pass it).
    unsigned base = 0;
    if (threadIdx.x == 0) base = atomicAdd(&g_bar_gen, 0u);

    // ---------------- Phase A: zero deg; block 0 computes v and const -----
    if (gtid < NZ) g_deg[gtid] = 0;
    if (blockIdx.x == 0) {
        if (threadIdx.x < NIN) {
            float s = 0.f;
            #pragma unroll
            for (int h = 0; h < NH; ++h) s += W[threadIdx.x * NH + h] * fcW[h];
            g_v[threadIdx.x] = s;
        } else if (threadIdx.x == NIN) {
            float s = fcb[0];
            #pragma unroll
            for (int h = 0; h < NH; ++h) s += bias[h] * fcW[h];
            g_const = s;
        }
    }
    grid_barrier(base + 1u);

    // ---------------- Phase B: histogram (+rank capture), then ydot -------
    if (gtid < NE) {
        int d = dst[gtid];
        g_rank[gtid] = atomicAdd(&g_deg[d], 1);   // rank within dst bucket
    }
    {
        const float4 vv = reinterpret_cast<const float4*>(g_v)[gtid & 7];
        const bool leader = (gtid & 7) == 0;
        const float4* xv = reinterpret_cast<const float4*>(x);
        // 6 full strides: front-load 6 independent 16B streaming loads.
        float4 a0 = __ldcs(&xv[gtid + 0 * GT]);
        float4 a1 = __ldcs(&xv[gtid + 1 * GT]);
        float4 a2 = __ldcs(&xv[gtid + 2 * GT]);
        float4 a3 = __ldcs(&xv[gtid + 3 * GT]);
        float4 a4 = __ldcs(&xv[gtid + 4 * GT]);
        float4 a5 = __ldcs(&xv[gtid + 5 * GT]);
        // tail load issued early too
        float4 a6;
        if (gtid < NYTAIL) a6 = __ldcs(&xv[gtid + 6 * GT]);

        float p0 = dot8(a0, vv);
        float p1 = dot8(a1, vv);
        float p2 = dot8(a2, vv);
        float p3 = dot8(a3, vv);
        float p4 = dot8(a4, vv);
        float p5 = dot8(a5, vv);
        if (leader) {
            emit_y(gtid + 0 * GT, p0);
            emit_y(gtid + 1 * GT, p1);
            emit_y(gtid + 2 * GT, p2);
            emit_y(gtid + 3 * GT, p3);
            emit_y(gtid + 4 * GT, p4);
            emit_y(gtid + 5 * GT, p5);
        }
        if (gtid < NYTAIL) {
            float p6 = dot8(a6, vv);
            if (leader) emit_y(gtid + 6 * GT, p6);
        }
    }
    grid_barrier(base + 2u);

    // ---------------- Phase C: dinv + exclusive scan (block 0) ------------
    if (gtid < NZ) g_dinv[gtid] = rsqrtf((float)(__ldcg(&g_deg[gtid]) + 1));
    if (blockIdx.x == 0) {
        __shared__ int warp_sums[32];
        const int CH = 4;                     // 1024*4 = 4096 >= NZ
        int t    = threadIdx.x;
        int lane = t & 31;
        int wid  = t >> 5;
        int bse  = t * CH;

        int local[CH];
        int s = 0;
        #pragma unroll
        for (int j = 0; j < CH; ++j) {
            int z = bse + j;
            int d = (z < NZ) ? __ldcg(&g_deg[z]) : 0;
            local[j] = s;
            s += d;
        }
        int v = s;
        #pragma unroll
        for (int o = 1; o < 32; o <<= 1) {
            int n = __shfl_up_sync(0xFFFFFFFFu, v, o);
            if (lane >= o) v += n;
        }
        if (lane == 31) warp_sums[wid] = v;
        __syncthreads();
        if (wid == 0) {
            int wv = warp_sums[lane];
            #pragma unroll
            for (int o = 1; o < 32; o <<= 1) {
                int n = __shfl_up_sync(0xFFFFFFFFu, wv, o);
                if (lane >= o) wv += n;
            }
            warp_sums[lane] = wv;             // inclusive warp sums
        }
        __syncthreads();
        int thread_excl = (v - s) + (wid > 0 ? warp_sums[wid - 1] : 0);
        #pragma unroll
        for (int j = 0; j < CH; ++j) {
            int z = bse + j;
            if (z < NZ) g_rowptr[z] = thread_excl + local[j];
        }
        if (t == 0) g_rowptr[NZ] = NE;
    }
    grid_barrier(base + 3u);

    // ---------------- Phase D: CSR fill (no atomics) -----------------------
    if (gtid < NE) {
        int s = src[gtid];
        int d = dst[gtid];
        int slot = g_rowptr[d] + g_rank[gtid];
        g_csr[slot] = make_float2(__int_as_float(s), g_dinv[s]);
    }
    grid_barrier(base + 4u);

    // ---------------- Phase E: gather + self-loop + transposed store ------
    {
        int warp = gtid >> 5;
        int lane = gtid & 31;                 // batch index
        const int NW = GT / 32;               // 4736 warps
        float c = g_const;
        for (int z = warp; z < NZ; z += NW) {
            int beg = g_rowptr[z];
            int end = g_rowptr[z + 1];
            float val = 0.f;
            int i = beg;
            for (; i + 4 <= end; i += 4) {
                float2 e0 = g_csr[i + 0];
                float2 e1 = g_csr[i + 1];
                float2 e2 = g_csr[i + 2];
                float2 e3 = g_csr[i + 3];
                float y0 = g_y[__float_as_int(e0.x) * NB + lane];
                float y1 = g_y[__float_as_int(e1.x) * NB + lane];
                float y2 = g_y[__float_as_int(e2.x) * NB + lane];
                float y3 = g_y[__float_as_int(e3.x) * NB + lane];
                val += e0.y * y0 + e1.y * y1 + e2.y * y2 + e3.y * y3;
            }
            for (; i < end; ++i) {
                float2 e = g_csr[i];
                val += e.y * g_y[__float_as_int(e.x) * NB + lane];
            }
            float dz = g_dinv[z];
            val = dz * (val + dz * g_y[z * NB + lane]);   // + self-loop
            out[(size_t)lane * NZ + z] = val + c;
        }
    }
}

// ---------------------------------------------------------------------------
extern "C" void kernel_launch(void* const* d_in, const int* in_sizes, int n_in,
                              void* d_out, int out_size) {
    const float* x    = (const float*)d_in[0];   // [32,4000,32]
    const int*   ei   = (const int*)  d_in[1];   // [2,64000]
    const float* W    = (const float*)d_in[2];   // [32,64]
    const float* bias = (const float*)d_in[3];   // [64]
    const float* fcW  = (const float*)d_in[4];   // [64]
    const float* fcb  = (const float*)d_in[5];   // [1]
    float* out = (float*)d_out;                  // [32,4000]

    k_fused<<<NBLK, NTHR>>>(x, ei, ei + NE, W, bias, fcW, fcb, out);
}

// round 6
// speedup vs baseline: 1.9697x; 1.4981x over previous
#include <cuda_runtime.h>
#include <cuda_bf16.h>
#include <cstdint>

// Problem constants (fixed by the reference)
#define NB 32      // batch
#define NZ 4000    // nodes
#define NIN 32     // in features
#define NH 64      // hidden
#define NE 64000   // edges

#define NY  (NB * NZ * NIN / 4)   // 1,024,000 float4 loads of x
#define NYB (NY / 256)            // 4000 ydot blocks
#define NEB ((NE + 255) / 256)    // 250 histogram blocks

// Scratch (device globals; no allocations allowed)
__device__ __align__(16) float g_y[NZ * NB];    // y[z*NB + b] = x[b,z,:] . v
__device__ __align__(16) float g_acc[NZ * NB];  // accumulator, [z][b]
__device__ int   g_deg[NZ];                     // in-degree EXCLUDING self-loop
__device__ __align__(16) float g_v[NIN];        // W @ fc_W
__device__ float g_const;                       // b . fc_W + fc_b

// ---------------------------------------------------------------------------
// K1: zero deg + acc; block 0 computes v = W@fc_W and the scalar const.
// grid = 125 blocks x 256 (covers NZ*NB/4 = 32000 float4 of acc, and NZ deg)
// ---------------------------------------------------------------------------
__global__ void k_init(const float* __restrict__ W,
                       const float* __restrict__ bias,
                       const float* __restrict__ fcW,
                       const float* __restrict__ fcb) {
    int t = blockIdx.x * blockDim.x + threadIdx.x;
    reinterpret_cast<float4*>(g_acc)[t] = make_float4(0.f, 0.f, 0.f, 0.f);
    if (t < NZ) g_deg[t] = 0;
    if (blockIdx.x == 0) {
        if (threadIdx.x < NIN) {
            float s = 0.f;
            #pragma unroll
            for (int h = 0; h < NH; ++h) s += W[threadIdx.x * NH + h] * fcW[h];
            g_v[threadIdx.x] = s;
        } else if (threadIdx.x == NIN) {
            float s = fcb[0];
            #pragma unroll
            for (int h = 0; h < NH; ++h) s += bias[h] * fcW[h];
            g_const = s;
        }
    }
}

// ---------------------------------------------------------------------------
// K2: fused ydot + degree histogram (independent work, both depend only on K1).
// Blocks [0, NYB): thread t loads float4 #t of x (flat, perfectly coalesced);
//   lanes 8k..8k+7 cover one (b,z) row; 3-step xor-shuffle reduce; leader
//   lane writes y[z*NB+b].
// Blocks [NYB, NYB+NEB): degree histogram over edge destinations.
// ---------------------------------------------------------------------------
__global__ void k_ydot_hist(const float* __restrict__ x,
                            const int* __restrict__ dst) {
    if (blockIdx.x < NYB) {
        int t = blockIdx.x * blockDim.x + threadIdx.x;   // < NY
        float4 xv = __ldcs(&reinterpret_cast<const float4*>(x)[t]);
        float4 vv = reinterpret_cast<const float4*>(g_v)[t & 7];
        float p = xv.x * vv.x + xv.y * vv.y + xv.z * vv.z + xv.w * vv.w;
        p += __shfl_xor_sync(0xFFFFFFFFu, p, 1);
        p += __shfl_xor_sync(0xFFFFFFFFu, p, 2);
        p += __shfl_xor_sync(0xFFFFFFFFu, p, 4);
        if ((t & 7) == 0) {
            int f = t >> 3;             // row index = b*NZ + z
            int b = f / NZ;
            int z = f - b * NZ;
            g_y[z * NB + b] = p;
        }
    } else {
        int e = (blockIdx.x - NYB) * blockDim.x + threadIdx.x;
        if (e < NE) atomicAdd(&g_deg[dst[e]], 1);
    }
}

// ---------------------------------------------------------------------------
// K3: edge scatter with VECTOR atomics. 8 threads per edge, each covers a
// float4 of the 32 batches: 512K float4 REDs instead of 2.05M scalar REDs
// (the LTS atomic unit is op-throughput bound, not byte bound).
// acc4[d*8+q] += norm * y4[s*8+q],  norm = rsqrt((deg_s+1)(deg_d+1)).
// ---------------------------------------------------------------------------
__global__ void k_scatter(const int* __restrict__ src,
                          const int* __restrict__ dst) {
    int t = blockIdx.x * blockDim.x + threadIdx.x;   // t = e*8 + q
    int e = t >> 3;
    int q = t & 7;
    if (e >= NE) return;
    int s = src[e];
    int d = dst[e];
    float norm = rsqrtf((float)((g_deg[s] + 1) * (g_deg[d] + 1)));
    float4 y4 = reinterpret_cast<const float4*>(g_y)[s * 8 + q];
    float4 m = make_float4(norm * y4.x, norm * y4.y, norm * y4.z, norm * y4.w);
    atomicAdd(&reinterpret_cast<float4*>(g_acc)[d * 8 + q], m);
}

// ---------------------------------------------------------------------------
// K4: out[b][z] = acc[z][b] + y[z][b]/(deg+1) + const, via 32x32 smem tile.
// ---------------------------------------------------------------------------
__global__ void k_out(float* __restrict__ out) {
    __shared__ float tile[32][33];
    int zb = blockIdx.x * 32;                 // NZ % 32 == 0 (4000 = 125*32)
    int z = zb + threadIdx.y;
    float invdeg = 1.0f / (float)(g_deg[z] + 1);   // broadcast within warp
    int idx = z * NB + threadIdx.x;
    tile[threadIdx.y][threadIdx.x] = g_acc[idx] + g_y[idx] * invdeg;
    __syncthreads();
    float c = g_const;
    out[(size_t)threadIdx.y * NZ + zb + threadIdx.x] = tile[threadIdx.x][threadIdx.y] + c;
}

// ---------------------------------------------------------------------------
extern "C" void kernel_launch(void* const* d_in, const int* in_sizes, int n_in,
                              void* d_out, int out_size) {
    const float* x    = (const float*)d_in[0];   // [32,4000,32]
    const int*   ei   = (const int*)  d_in[1];   // [2,64000]
    const float* W    = (const float*)d_in[2];   // [32,64]
    const float* bias = (const float*)d_in[3];   // [64]
    const float* fcW  = (const float*)d_in[4];   // [64]
    const float* fcb  = (const float*)d_in[5];   // [1]
    float* out = (float*)d_out;                  // [32,4000]

    const int* src = ei;
    const int* dst = ei + NE;

    k_init<<<(NZ * NB / 4) / 256, 256>>>(W, bias, fcW, fcb);
    k_ydot_hist<<<NYB + NEB, 256>>>(x, dst);
    k_scatter<<<(NE * 8) / 256, 256>>>(src, dst);
    k_out<<<NZ / 32, dim3(32, 32)>>>(out);
}